// round 9
// baseline (speedup 1.0000x reference)
#include <cuda_runtime.h>
#include <cstdint>

#define Bn 8
#define Hn 64
#define Wn 64
#define HW 4096
#define KK 9
#define EPSV 1e-4f
#define SA 136   // wn_s row stride (136 mod 32 = 8): q*8+2g unique -> conflict-free LDS.64
#define SB 40    // cols_s row stride (40 mod 32 = 8): g*8+2q unique -> conflict-free LDS.64

#define WN_FL   (32 * SA)                   // 4352 floats per wn stage
#define COL_FL  (128 * SB)                  // 5120 floats per cols stage (128 px)
#define SMEM_FL (2 * (WN_FL + COL_FL))      // 18944 floats = 75776 B per CTA

__device__ float g_xt[Bn * HW * 128];       // x transposed [b][hw][c]
__device__ float g_wnt[KK * 128 * 128];     // normalized wn [k][c][o-permuted], tf32

__device__ __forceinline__ float to_tf32(float x) {
    float r; asm("cvt.rna.tf32.f32 %0, %1;" : "=f"(r) : "f"(x)); return r;
}
__device__ __forceinline__ uint32_t smem_u32(const void* p) {
    uint32_t a;
    asm("{ .reg .u64 t; cvta.to.shared.u64 t, %1; cvt.u32.u64 %0, t; }" : "=r"(a) : "l"(p));
    return a;
}
__device__ __forceinline__ void mma_tf32(float* d, const uint32_t* a, const uint32_t* b) {
    asm volatile(
        "mma.sync.aligned.m16n8k8.row.col.f32.tf32.tf32.f32 "
        "{%0,%1,%2,%3}, {%4,%5,%6,%7}, {%8,%9}, {%0,%1,%2,%3};"
        : "+f"(d[0]), "+f"(d[1]), "+f"(d[2]), "+f"(d[3])
        : "r"(a[0]), "r"(a[1]), "r"(a[2]), "r"(a[3]), "r"(b[0]), "r"(b[1]));
}
#define CP_ASYNC16(dst, src) \
    asm volatile("cp.async.ca.shared.global [%0], [%1], 16;" :: "r"(dst), "l"(src) : "memory")
#define CP_COMMIT()  asm volatile("cp.async.commit_group;" ::: "memory")
#define CP_WAIT0()   asm volatile("cp.async.wait_group 0;" ::: "memory")

// bilinear gather parameters for one (pixel, k)
struct GP {
    const float *p00, *p01, *p10, *p11;
    float w00, w01, w10, w11;
};
__device__ __forceinline__ GP gparams(const float* __restrict__ xb,
                                      const float* __restrict__ offset,
                                      int b, int k, int gho, int gwo) {
    const int ky = k / 3, kx = k - ky * 3;
    const float offy = __ldg(&offset[(((b * 18) + 2 * k    ) * Hn + gho) * Wn + gwo]);
    const float offx = __ldg(&offset[(((b * 18) + 2 * k + 1) * Hn + gho) * Wn + gwo]);
    const float py  = (float)(gho - 1 + ky) + offy;
    const float pxf = (float)(gwo - 1 + kx) + offx;
    const float y0f = floorf(py), x0f = floorf(pxf);
    const float ly = py - y0f, lx = pxf - x0f;
    const int y0 = (int)y0f, x0 = (int)x0f, y1 = y0 + 1, x1 = x0 + 1;
    GP g;
    g.w00 = (1.f - ly) * (1.f - lx); g.w01 = (1.f - ly) * lx;
    g.w10 = ly * (1.f - lx);         g.w11 = ly * lx;
    if (!((y0 >= 0) & (y0 < Hn) & (x0 >= 0) & (x0 < Wn))) g.w00 = 0.f;
    if (!((y0 >= 0) & (y0 < Hn) & (x1 >= 0) & (x1 < Wn))) g.w01 = 0.f;
    if (!((y1 >= 0) & (y1 < Hn) & (x0 >= 0) & (x0 < Wn))) g.w10 = 0.f;
    if (!((y1 >= 0) & (y1 < Hn) & (x1 >= 0) & (x1 < Wn))) g.w11 = 0.f;
    const int yc0 = min(max(y0, 0), Hn - 1), yc1 = min(max(y1, 0), Hn - 1);
    const int xc0 = min(max(x0, 0), Wn - 1), xc1 = min(max(x1, 0), Wn - 1);
    g.p00 = xb + (size_t)(yc0 * Wn + xc0) * 128;
    g.p01 = xb + (size_t)(yc0 * Wn + xc1) * 128;
    g.p10 = xb + (size_t)(yc1 * Wn + xc0) * 128;
    g.p11 = xb + (size_t)(yc1 * Wn + xc1) * 128;
    return g;
}

// ---- kernel 1: prep = transpose x + normalize weights ----
__global__ void prep_kernel(const float* __restrict__ x, const float* __restrict__ w) {
    if (blockIdx.x < 4096) {
        __shared__ float s[32][33];
        int id = blockIdx.x;
        int b = id >> 9, rest = id & 511;
        int c0 = (rest >> 7) * 32, hw0 = (rest & 127) * 32;
        int tx = threadIdx.x & 31, ty = threadIdx.x >> 5;
        #pragma unroll
        for (int p = 0; p < 4; p++)
            s[ty + p * 8][tx] = x[(size_t)(b * 128 + c0 + ty + p * 8) * HW + hw0 + tx];
        __syncthreads();
        #pragma unroll
        for (int p = 0; p < 4; p++)
            g_xt[(size_t)(b * HW + hw0 + ty + p * 8) * 128 + c0 + tx] = s[tx][ty + p * 8];
    } else {
        int k = blockIdx.x - 4096;
        int o = threadIdx.x;
        if (o < 128) {
            float s = 0.f;
            #pragma unroll 8
            for (int c = 0; c < 128; c++) { float v = w[(o * 128 + c) * KK + k]; s += v * v; }
            float inv = 1.0f / (sqrtf(s + 128.0f * EPSV) * 3.0f);
            // o-permuted position: rows (g, g+8) of each 16-block adjacent
            const int opos = (o >> 4) * 16 + (o & 7) * 2 + ((o >> 3) & 1);
            #pragma unroll 8
            for (int c = 0; c < 128; c++)
                g_wnt[(k * 128 + c) * 128 + opos] = to_tf32(w[(o * 128 + c) * KK + k] * inv);
        }
    }
}

// ---- kernel 2: main — pipelined im2col gather + tf32 mma.sync GEMM ----
// grid 256, 256 thr, 2 CTAs/SM. block = (b, 2 rows): D[128co][128px],
// 8 warps = 4m x 2n, each 32co x 64px. Pair-packed smem: all frag loads LDS.64.
__global__ __launch_bounds__(256, 2)
void deform_main_kernel(const float* __restrict__ offset, float* __restrict__ out) {
    extern __shared__ float sm[];
    float* wnb[2]  = { sm, sm + WN_FL };
    float* colb[2] = { sm + 2 * WN_FL, sm + 2 * WN_FL + COL_FL };
    const uint32_t wnb_u32[2] = { smem_u32(wnb[0]), smem_u32(wnb[1]) };

    const int t = threadIdx.x;
    const int b = blockIdx.x >> 5;
    const int ho0 = (blockIdx.x & 31) * 2;

    // gather mapping: 2 threads per pixel (128 px), 16 channels each
    const int gpx = t >> 1, h = t & 1;
    const int gho = ho0 + (gpx >> 6), gwo = gpx & 63;
    // mma mapping: 8 warps = 4m x 2n
    const int w = t >> 5, lane = t & 31;
    const int m0 = (w & 3) * 32, n0 = (w >> 2) * 64;
    const int g = lane >> 2, q = lane & 3;
    const int mblk = (m0 >> 4);              // base 16-block index of this warp

    float acc[2][8][4];
    #pragma unroll
    for (int mt = 0; mt < 2; mt++)
        #pragma unroll
        for (int nt = 0; nt < 8; nt++)
            #pragma unroll
            for (int r = 0; r < 4; r++) acc[mt][nt][r] = 0.f;

    const float* xb = g_xt + (size_t)b * HW * 128;

    // ---- prologue: gather chunk 0 into colb[0], cp.async wn chunk 0 ----
    GP gp = gparams(xb, offset, b, 0, gho, gwo);
    {
        float v[16];
        #pragma unroll
        for (int sub = 0; sub < 4; sub++) {
            const int co = h * 16 + sub * 4;
            float4 a = *(const float4*)(gp.p00 + co);
            float4 bb = *(const float4*)(gp.p01 + co);
            float4 c = *(const float4*)(gp.p10 + co);
            float4 d = *(const float4*)(gp.p11 + co);
            v[sub*4+0] = to_tf32(gp.w00 * a.x + gp.w01 * bb.x + gp.w10 * c.x + gp.w11 * d.x);
            v[sub*4+1] = to_tf32(gp.w00 * a.y + gp.w01 * bb.y + gp.w10 * c.y + gp.w11 * d.y);
            v[sub*4+2] = to_tf32(gp.w00 * a.z + gp.w01 * bb.z + gp.w10 * c.z + gp.w11 * d.z);
            v[sub*4+3] = to_tf32(gp.w00 * a.w + gp.w01 * bb.w + gp.w10 * c.w + gp.w11 * d.w);
        }
        // pair-packed store: groups 2h, 2h+1; pair (c, c+4) adjacent
        #pragma unroll
        for (int gr = 0; gr < 2; gr++)
            #pragma unroll
            for (int j = 0; j < 4; j++)
                *(float2*)&colb[0][gpx * SB + h * 16 + gr * 8 + j * 2] =
                    make_float2(v[gr * 8 + j], v[gr * 8 + j + 4]);
        const float* src = g_wnt;   // chunk 0
        #pragma unroll
        for (int p = 0; p < 4; p++) {
            int e16 = p * 256 + t;
            int c = e16 >> 5, off = (e16 & 31) * 4;
            CP_ASYNC16(wnb_u32[0] + (uint32_t)(c * SA + off) * 4, src + e16 * 4);
        }
        CP_COMMIT();
        CP_WAIT0();
    }

    // ---- pipelined main loop over 36 chunks ----
    for (int it = 0; it < 36; it++) {
        const int cur = it & 1, nxt = cur ^ 1;
        __syncthreads();

        const bool more = (it + 1 < 36);
        if (more) {
            const float* src = g_wnt + (size_t)(it + 1) * 4096;
            #pragma unroll
            for (int p = 0; p < 4; p++) {
                int e16 = p * 256 + t;
                int c = e16 >> 5, off = (e16 & 31) * 4;
                CP_ASYNC16(wnb_u32[nxt] + (uint32_t)(c * SA + off) * 4, src + e16 * 4);
            }
            CP_COMMIT();
            if (((it + 1) & 3) == 0)
                gp = gparams(xb, offset, b, (it + 1) >> 2, gho, gwo);
        }
        const int ccn = (it + 1) & 3;
        const float* wnc = wnb[cur];
        const float* colc = colb[cur];
        float* coln = colb[nxt];

        #pragma unroll
        for (int sub = 0; sub < 4; sub++) {
            // issue next-chunk corner loads (hidden under this sub's MMAs)
            float4 a, bb, c, d;
            if (more) {
                const int co = ccn * 32 + h * 16 + sub * 4;   // global channel
                a  = *(const float4*)(gp.p00 + co);
                bb = *(const float4*)(gp.p01 + co);
                c  = *(const float4*)(gp.p10 + co);
                d  = *(const float4*)(gp.p11 + co);
            }
            // MMA k-step: all fragment loads are LDS.64 on pair-packed layouts
            const int c8 = sub * 8;
            uint32_t af[2][4];
            #pragma unroll
            for (int mt = 0; mt < 2; mt++) {
                float2 pa = *(const float2*)&wnc[(c8 + q) * SA + (mblk + mt) * 16 + g * 2];
                float2 pb = *(const float2*)&wnc[(c8 + q + 4) * SA + (mblk + mt) * 16 + g * 2];
                af[mt][0] = __float_as_uint(pa.x);
                af[mt][1] = __float_as_uint(pa.y);
                af[mt][2] = __float_as_uint(pb.x);
                af[mt][3] = __float_as_uint(pb.y);
            }
            uint32_t bf[8][2];
            #pragma unroll
            for (int nt = 0; nt < 8; nt++) {
                const int px = n0 + nt * 8 + g;
                float2 pv = *(const float2*)&colc[px * SB + sub * 8 + q * 2];
                bf[nt][0] = __float_as_uint(pv.x);
                bf[nt][1] = __float_as_uint(pv.y);
            }
            #pragma unroll
            for (int mt = 0; mt < 2; mt++)
                #pragma unroll
                for (int nt = 0; nt < 8; nt++)
                    mma_tf32(acc[mt][nt], af[mt], bf[nt]);

            // blend + pair-packed store of next-chunk quad
            if (more) {
                float v0 = to_tf32(gp.w00 * a.x + gp.w01 * bb.x + gp.w10 * c.x + gp.w11 * d.x);
                float v1 = to_tf32(gp.w00 * a.y + gp.w01 * bb.y + gp.w10 * c.y + gp.w11 * d.y);
                float v2 = to_tf32(gp.w00 * a.z + gp.w01 * bb.z + gp.w10 * c.z + gp.w11 * d.z);
                float v3 = to_tf32(gp.w00 * a.w + gp.w01 * bb.w + gp.w10 * c.w + gp.w11 * d.w);
                // this quad covers channels (h*16 + sub*4 .. +3) of the chunk:
                // group gr = (h*16+sub*4)/8 = h*2 + sub/2, j0 = (sub&1)*4? No:
                // channels c..c+3 map to pairs: pair index = (ch mod 8) paired with +4.
                const int chb = h * 16 + sub * 4;        // local channel base
                const int gr = chb >> 3;                 // 8-channel group
                const int jo = chb & 7;                  // 0 or 4 within group
                if (jo == 0) {
                    // channels gr*8 + {0,1,2,3}: first halves of pairs 0..3
                    coln[gpx * SB + gr * 8 + 0] = v0;
                    coln[gpx * SB + gr * 8 + 2] = v1;
                    coln[gpx * SB + gr * 8 + 4] = v2;
                    coln[gpx * SB + gr * 8 + 6] = v3;
                } else {
                    // channels gr*8 + {4,5,6,7}: second halves of pairs 0..3
                    coln[gpx * SB + gr * 8 + 1] = v0;
                    coln[gpx * SB + gr * 8 + 3] = v1;
                    coln[gpx * SB + gr * 8 + 5] = v2;
                    coln[gpx * SB + gr * 8 + 7] = v3;
                }
            }
        }
        if (more) CP_WAIT0();
    }

    // ---- epilogue: out[b][cout][ho][wo] ----
    const int ho = ho0 + (n0 >> 6);
    #pragma unroll
    for (int mt = 0; mt < 2; mt++) {
        const int r0 = m0 + mt * 16 + g;
        #pragma unroll
        for (int nt = 0; nt < 8; nt++) {
            const int wo = nt * 8 + 2 * q;
            float2 v0 = make_float2(acc[mt][nt][0], acc[mt][nt][1]);
            float2 v1 = make_float2(acc[mt][nt][2], acc[mt][nt][3]);
            *(float2*)&out[((size_t)(b * 128 + r0)     * HW) + ho * Wn + wo] = v0;
            *(float2*)&out[((size_t)(b * 128 + r0 + 8) * HW) + ho * Wn + wo] = v1;
        }
    }
}

// ---------------------------------------------------------------------------
extern "C" void kernel_launch(void* const* d_in, const int* in_sizes, int n_in,
                              void* d_out, int out_size) {
    const float* x      = (const float*)d_in[0];   // (8,128,64,64)
    const float* offset = (const float*)d_in[1];   // (8,18,64,64)
    const float* weight = (const float*)d_in[2];   // (128,128,3,3)
    float* out = (float*)d_out;                    // (8,128,64,64)

    cudaFuncSetAttribute(deform_main_kernel,
                         cudaFuncAttributeMaxDynamicSharedMemorySize, SMEM_FL * 4);
    prep_kernel<<<4105, 256>>>(x, weight);
    deform_main_kernel<<<256, 256, SMEM_FL * 4>>>(offset, out);
}